// round 4
// baseline (speedup 1.0000x reference)
#include <cuda_runtime.h>

// streams [B=4, N=8, T=2048, D=1024] fp32, logits [8,8] fp32.
// out[b,i,t,d] = sum_j H[i,j] * streams[b,j,t,d], H = sinkhorn(logits), temp=1.
//
// Single fused persistent kernel:
//   - every block resident from t=0 (grid = 148 SMs x 4 blocks, 64-reg cap)
//   - all warps prefetch their first tile, warp 0 computes sinkhorn meanwhile
//   - grid-stride loop over work quanta (256 float4 positions each)

#define NS         8
#define SINK_ITERS 20
#define SINK_EPS   1e-8f
#define B_DIM      4
#define TD4        (2048 * 1024 / 4)   // float4 per (b,j) slice = 1<<19
#define TD4_LOG2   19
#define NQ         (B_DIM * TD4 / 256) // 8192 work quanta
#define GRID       (148 * 4)

__global__ void __launch_bounds__(256, 4)
fused_mixer_kernel(const float4* __restrict__ in,
                   const float*  __restrict__ logits,
                   float4* __restrict__ out) {
    __shared__ float sH[NS * NS];

    // ---- issue first-quantum loads (independent of H) ----
    int q = blockIdx.x;
    int pos  = (q << 8) + threadIdx.x;       // [0, B*TD4)
    int b    = pos >> TD4_LOG2;
    int r    = pos & (TD4 - 1);
    int base = b * (NS * TD4) + r;

    float4 v[NS];
    #pragma unroll
    for (int j = 0; j < NS; j++) v[j] = __ldcs(&in[base + j * TD4]);

    // ---- warp 0: warp-parallel sinkhorn (overlaps the in-flight loads) ----
    // Lane l owns e0 = (row=l>>3, col=l&7) and e1 = (row+4, col).
    if (threadIdx.x < 32) {
        const unsigned FULL = 0xFFFFFFFFu;
        int lane = threadIdx.x;
        float x0 = logits[lane];
        float x1 = logits[lane + 32];

        float m0 = x0, m1 = x1;
        #pragma unroll
        for (int m = 1; m <= 4; m <<= 1) {
            m0 = fmaxf(m0, __shfl_xor_sync(FULL, m0, m));
            m1 = fmaxf(m1, __shfl_xor_sync(FULL, m1, m));
        }
        float p0 = expf(x0 - m0) + SINK_EPS;
        float p1 = expf(x1 - m1) + SINK_EPS;

        for (int it = 0; it < SINK_ITERS; it++) {
            // row normalize
            float s0 = p0, s1 = p1;
            #pragma unroll
            for (int m = 1; m <= 4; m <<= 1) {
                s0 += __shfl_xor_sync(FULL, s0, m);
                s1 += __shfl_xor_sync(FULL, s1, m);
            }
            p0 = p0 / (s0 + SINK_EPS);
            p1 = p1 / (s1 + SINK_EPS);
            // col normalize (e0,e1 share a column; rows split over shfl 8,16)
            float c = p0 + p1;
            c += __shfl_xor_sync(FULL, c, 8);
            c += __shfl_xor_sync(FULL, c, 16);
            float inv = 1.0f / (c + SINK_EPS);
            p0 *= inv;
            p1 *= inv;
        }
        sH[lane]      = p0;
        sH[lane + 32] = p1;
    }
    __syncthreads();

    // ---- persistent grid-stride loop ----
    while (true) {
        #pragma unroll
        for (int i = 0; i < NS; i++) {
            float4 a = make_float4(0.f, 0.f, 0.f, 0.f);
            #pragma unroll
            for (int j = 0; j < NS; j++) {
                float h = sH[i * NS + j];
                a.x = fmaf(h, v[j].x, a.x);
                a.y = fmaf(h, v[j].y, a.y);
                a.z = fmaf(h, v[j].z, a.z);
                a.w = fmaf(h, v[j].w, a.w);
            }
            __stcs(&out[base + i * TD4], a);
        }

        q += GRID;
        if (q >= NQ) break;

        pos  = (q << 8) + threadIdx.x;
        b    = pos >> TD4_LOG2;
        r    = pos & (TD4 - 1);
        base = b * (NS * TD4) + r;
        #pragma unroll
        for (int j = 0; j < NS; j++) v[j] = __ldcs(&in[base + j * TD4]);
    }
}

extern "C" void kernel_launch(void* const* d_in, const int* in_sizes, int n_in,
                              void* d_out, int out_size) {
    const float4* streams = (const float4*)d_in[0];
    const float*  logits  = (const float*)d_in[1];
    float4* out = (float4*)d_out;

    fused_mixer_kernel<<<GRID, 256>>>(streams, logits, out);
}

// round 12
// speedup vs baseline: 1.0885x; 1.0885x over previous
#include <cuda_runtime.h>

// streams [B=4, N=8, T=2048, D=1024] fp32, logits [8,8] fp32.
// out[b,i,t,d] = sum_j H[i,j] * streams[b,j,t,d], H = sinkhorn(logits), temp=1.
//
// Two kernels with Programmatic Dependent Launch:
//   sinkhorn_kernel (1 warp) -> trigger -> mix_kernel launches early, issues
//   its 8 independent loads, then griddepsync before consuming d_H.

#define NS         8
#define SINK_ITERS 20
#define SINK_EPS   1e-8f
#define B_DIM      4
#define TD4        (2048 * 1024 / 4)   // float4 per (b,j) slice = 1<<19
#define TD4_LOG2   19

__device__ float d_H[NS * NS];

// ---------------------------------------------------------------------------
// Kernel 1: warp-parallel Sinkhorn. Lane l owns (row=l>>3, col=l&7) and
// (row+4, col). Row reduce: shfl_xor 1,2,4. Col reduce: e0+e1, shfl_xor 8,16.
// ---------------------------------------------------------------------------
__global__ void sinkhorn_kernel(const float* __restrict__ logits) {
    const unsigned FULL = 0xFFFFFFFFu;
    int lane = threadIdx.x;
    float x0 = logits[lane];
    float x1 = logits[lane + 32];

    float m0 = x0, m1 = x1;
    #pragma unroll
    for (int m = 1; m <= 4; m <<= 1) {
        m0 = fmaxf(m0, __shfl_xor_sync(FULL, m0, m));
        m1 = fmaxf(m1, __shfl_xor_sync(FULL, m1, m));
    }
    float p0 = expf(x0 - m0) + SINK_EPS;
    float p1 = expf(x1 - m1) + SINK_EPS;

    for (int it = 0; it < SINK_ITERS; it++) {
        float s0 = p0, s1 = p1;
        #pragma unroll
        for (int m = 1; m <= 4; m <<= 1) {
            s0 += __shfl_xor_sync(FULL, s0, m);
            s1 += __shfl_xor_sync(FULL, s1, m);
        }
        p0 = p0 / (s0 + SINK_EPS);
        p1 = p1 / (s1 + SINK_EPS);

        float c = p0 + p1;
        c += __shfl_xor_sync(FULL, c, 8);
        c += __shfl_xor_sync(FULL, c, 16);
        float inv = 1.0f / (c + SINK_EPS);
        p0 *= inv;
        p1 *= inv;
    }

    d_H[lane]      = p0;
    d_H[lane + 32] = p1;
    __threadfence();                               // publish before trigger
    cudaTriggerProgrammaticLaunchCompletion();     // let mix launch now
}

// ---------------------------------------------------------------------------
// Kernel 2: the mix (identical memory structure to the 80.5us R2 kernel).
// One thread per float4 position; 8 streaming loads -> griddepsync -> H ->
// 8 FMA-mixed streaming stores. 256MB read + 256MB write, 1x each.
// ---------------------------------------------------------------------------
__global__ void __launch_bounds__(256)
mix_kernel(const float4* __restrict__ in, float4* __restrict__ out) {
    int pos = blockIdx.x * blockDim.x + threadIdx.x;   // [0, B*TD4)
    int b = pos >> TD4_LOG2;
    int r = pos & (TD4 - 1);
    int base = b * (NS * TD4) + r;

    // Independent of H: issue all 8 loads before waiting on the primary.
    float4 v[NS];
    #pragma unroll
    for (int j = 0; j < NS; j++) v[j] = __ldcs(&in[base + j * TD4]);

    // Wait for sinkhorn's published writes (no-op if kernels serialized).
    cudaGridDependencySynchronize();

    __shared__ float sH[NS * NS];
    if (threadIdx.x < NS * NS) sH[threadIdx.x] = d_H[threadIdx.x];
    __syncthreads();

    #pragma unroll
    for (int i = 0; i < NS; i++) {
        float4 a = make_float4(0.f, 0.f, 0.f, 0.f);
        #pragma unroll
        for (int j = 0; j < NS; j++) {
            float h = sH[i * NS + j];
            a.x = fmaf(h, v[j].x, a.x);
            a.y = fmaf(h, v[j].y, a.y);
            a.z = fmaf(h, v[j].z, a.z);
            a.w = fmaf(h, v[j].w, a.w);
        }
        __stcs(&out[base + i * TD4], a);
    }
}

extern "C" void kernel_launch(void* const* d_in, const int* in_sizes, int n_in,
                              void* d_out, int out_size) {
    const float4* streams = (const float4*)d_in[0];
    const float*  logits  = (const float*)d_in[1];
    float4* out = (float4*)d_out;

    sinkhorn_kernel<<<1, 32>>>(logits);

    // Mix with programmatic dependent launch: overlaps its block launch +
    // load prologue with the sinkhorn kernel.
    cudaLaunchConfig_t cfg = {};
    cfg.gridDim  = dim3((B_DIM * TD4) / 256);
    cfg.blockDim = dim3(256);
    cfg.dynamicSmemBytes = 0;
    cfg.stream = 0;

    cudaLaunchAttribute attrs[1];
    attrs[0].id = cudaLaunchAttributeProgrammaticStreamSerialization;
    attrs[0].val.programmaticStreamSerializationAllowed = 1;
    cfg.attrs = attrs;
    cfg.numAttrs = 1;

    cudaLaunchKernelEx(&cfg, mix_kernel, streams, out);
}